// round 3
// baseline (speedup 1.0000x reference)
#include <cuda_runtime.h>

#define B_  32
#define T_  12
#define N_  512
#define E_  10
#define K_  3
#define CI_ 64
#define CO_ 64

// Scratch (static device globals -- allocation-free per harness rules)
__device__ float g_A[(size_t)T_ * N_ * N_];        // 12.6 MB adjacency (post-softmax)
__device__ float g_diag2[T_ * N_];                  // 2 * diag(A)
__device__ float g_xg1[(size_t)B_ * T_ * N_ * CI_]; // 50 MB propagated features (k=1)

// ---------------------------------------------------------------------------
// Kernel 1: A[t] = softmax(relu(emb[t] @ emb[t]^T), axis=-1), plus 2*diag(A).
// One block per (t, n) row; emb[t] (20 KB) cached in SMEM.
// ---------------------------------------------------------------------------
__global__ void __launch_bounds__(256) k_adj(const float* __restrict__ emb) {
    const int t = blockIdx.y, n = blockIdx.x;
    __shared__ float se[N_ * E_];
    __shared__ float red[256];
    const float* et = emb + (size_t)t * N_ * E_;
    for (int i = threadIdx.x; i < N_ * E_; i += 256) se[i] = et[i];
    __syncthreads();

    float en[E_];
#pragma unroll
    for (int e = 0; e < E_; e++) en[e] = se[n * E_ + e];

    const int s0 = threadIdx.x, s1 = threadIdx.x + 256;
    float v0 = 0.f, v1 = 0.f;
#pragma unroll
    for (int e = 0; e < E_; e++) {
        v0 = fmaf(en[e], se[s0 * E_ + e], v0);
        v1 = fmaf(en[e], se[s1 * E_ + e], v1);
    }
    v0 = fmaxf(v0, 0.f);
    v1 = fmaxf(v1, 0.f);

    // block max
    red[threadIdx.x] = fmaxf(v0, v1);
    __syncthreads();
    for (int off = 128; off > 0; off >>= 1) {
        if (threadIdx.x < off) red[threadIdx.x] = fmaxf(red[threadIdx.x], red[threadIdx.x + off]);
        __syncthreads();
    }
    const float m = red[0];
    __syncthreads();

    const float e0 = expf(v0 - m), e1 = expf(v1 - m);
    red[threadIdx.x] = e0 + e1;
    __syncthreads();
    for (int off = 128; off > 0; off >>= 1) {
        if (threadIdx.x < off) red[threadIdx.x] += red[threadIdx.x + off];
        __syncthreads();
    }
    const float inv = 1.0f / red[0];

    float* arow = g_A + ((size_t)t * N_ + n) * N_;
    arow[s0] = e0 * inv;
    arow[s1] = e1 * inv;
    if (threadIdx.x == (n & 255)) {
        const float dv = (n < 256 ? e0 : e1) * inv;
        g_diag2[t * N_ + n] = 2.0f * dv;
    }
}

// ---------------------------------------------------------------------------
// Kernel 2: xg1[b,t,n,c] = sum_m A[t,n,m] * x[b,t,m,c]
// Per (b,t): GEMM M=512(n) x N=64(c) x K=512(m). Tile BM=128, BN=64, BK=16.
// 256 threads, 8x4 register tile.
// ---------------------------------------------------------------------------
__global__ void __launch_bounds__(256) k_spmm(const float* __restrict__ x) {
    const int bt = blockIdx.y;                 // b*T + t
    const int t  = bt % T_;
    const int n0 = blockIdx.x * 128;

    __shared__ __align__(16) float As[16][132]; // As[k][n], padded
    __shared__ __align__(16) float Xs[16][68];  // Xs[k][c], padded

    const float* Abase = g_A + ((size_t)t * N_ + n0) * N_;
    const float* Xbase = x + (size_t)bt * N_ * CI_;

    const int tid = threadIdx.x;
    const int ty = tid >> 4, tx = tid & 15;      // 16x16 thread grid
    const int ar = tid >> 2;                      // 0..63 (A tile rows, x2)
    const int ac = (tid & 3) * 4;                 // 0,4,8,12
    const int xr = tid >> 4;                      // 0..15
    const int xc = (tid & 15) * 4;                // 0..60

    float acc[8][4];
#pragma unroll
    for (int i = 0; i < 8; i++)
#pragma unroll
        for (int j = 0; j < 4; j++) acc[i][j] = 0.f;

    for (int m0 = 0; m0 < N_; m0 += 16) {
        __syncthreads();
#pragma unroll
        for (int r = 0; r < 2; r++) {
            const int row = r * 64 + ar;
            float4 av = *(const float4*)(Abase + (size_t)row * N_ + m0 + ac);
            As[ac + 0][row] = av.x;
            As[ac + 1][row] = av.y;
            As[ac + 2][row] = av.z;
            As[ac + 3][row] = av.w;
        }
        {
            float4 xv = *(const float4*)(Xbase + (size_t)(m0 + xr) * CI_ + xc);
            *(float4*)&Xs[xr][xc] = xv;
        }
        __syncthreads();
#pragma unroll
        for (int kk = 0; kk < 16; kk++) {
            float4 a0 = *(const float4*)&As[kk][ty * 8];
            float4 a1 = *(const float4*)&As[kk][ty * 8 + 4];
            float4 xx = *(const float4*)&Xs[kk][tx * 4];
            float a[8] = {a0.x, a0.y, a0.z, a0.w, a1.x, a1.y, a1.z, a1.w};
            float xv[4] = {xx.x, xx.y, xx.z, xx.w};
#pragma unroll
            for (int i = 0; i < 8; i++)
#pragma unroll
                for (int j = 0; j < 4; j++) acc[i][j] = fmaf(a[i], xv[j], acc[i][j]);
        }
    }

    float* obase = g_xg1 + (size_t)bt * N_ * CI_;
#pragma unroll
    for (int i = 0; i < 8; i++) {
        const int n = n0 + ty * 8 + i;
        float4 o;
        o.x = acc[i][0]; o.y = acc[i][1]; o.z = acc[i][2]; o.w = acc[i][3];
        *(float4*)(obase + (size_t)n * CI_ + tx * 4) = o;
    }
}

// ---------------------------------------------------------------------------
// Kernel 3: fused theta-generation + output contraction + bias + relu.
// Block = (t, 8-node tile). For each ki-chunk of 16 (of K*Ci=192):
//   theta_chunk[nl][kic][o] = sum_d emb[n,d] * W[t,d,k,i,o]   (W hot in L2)
//   xg chunk from x / g_xg1 / (2*diag*xg1 - x)
//   acc[b][o] += xg * theta   (8 small GEMM steps)
// ---------------------------------------------------------------------------
#define SMEM_FLOATS (8 * 16 * 64 + 8 * 16 * 32 + 8 * 64 + 96 + 8)

__global__ void __launch_bounds__(256) k_out(const float* __restrict__ x,
                                             const float* __restrict__ emb,
                                             const float* __restrict__ W,
                                             const float* __restrict__ bp,
                                             float* __restrict__ out) {
    extern __shared__ __align__(16) float sm[];
    float* theta_s = sm;                        // 8192
    float* xg_s    = sm + 8192;                 // 4096
    float* bias_s  = sm + 8192 + 4096;          // 512
    float* emb_s   = bias_s + 512;              // 80 (padded 96)
    float* d2_s    = emb_s + 96;                // 8

    const int t  = blockIdx.y;
    const int n0 = blockIdx.x * 8;
    const int tid = threadIdx.x;

    if (tid < 8 * E_)
        emb_s[tid] = emb[((size_t)t * N_ + n0 + tid / E_) * E_ + (tid % E_)];
    if (tid < 8) d2_s[tid] = g_diag2[t * N_ + n0 + tid];
    __syncthreads();

    // bias[nl][o] = sum_d emb[nl][d] * bias_pool[t,d,o]
    for (int ii = tid; ii < 8 * CO_; ii += 256) {
        const int nl = ii >> 6, o = ii & 63;
        float v = 0.f;
#pragma unroll
        for (int d = 0; d < E_; d++)
            v = fmaf(emb_s[nl * E_ + d], bp[((size_t)t * E_ + d) * CO_ + o], v);
        bias_s[ii] = v;
    }

    const int g  = tid >> 5;        // node within tile
    const int w  = tid & 31;
    const int bq = w >> 3;          // batch quad  (b = bq*8 .. +7)
    const int oq = w & 7;           // out-chan oct (o = oq*8 .. +7)

    const int lnl = tid >> 5, lb = tid & 31;    // staging map: one (node,batch) row each
    const float* xrow  = x     + (((size_t)lb * T_ + t) * N_ + n0 + lnl) * CI_;
    const float* x1row = g_xg1 + (((size_t)lb * T_ + t) * N_ + n0 + lnl) * CI_;
    const float d2 = d2_s[lnl];

    float acc[8][8];
#pragma unroll
    for (int i = 0; i < 8; i++)
#pragma unroll
        for (int j = 0; j < 8; j++) acc[i][j] = 0.f;

    for (int c = 0; c < 12; c++) {
        const int k  = c >> 2;
        const int i0 = (c & 3) * 16;
        __syncthreads();

        // --- stage xg chunk: xg_s[nl][kic][b] ---
#pragma unroll
        for (int j4 = 0; j4 < 4; j4++) {
            float4 xv;
            if (k == 0) {
                xv = *(const float4*)(xrow + i0 + j4 * 4);
            } else if (k == 1) {
                xv = *(const float4*)(x1row + i0 + j4 * 4);
            } else {
                float4 a  = *(const float4*)(x1row + i0 + j4 * 4);
                float4 bb = *(const float4*)(xrow + i0 + j4 * 4);
                xv.x = fmaf(d2, a.x, -bb.x);
                xv.y = fmaf(d2, a.y, -bb.y);
                xv.z = fmaf(d2, a.z, -bb.z);
                xv.w = fmaf(d2, a.w, -bb.w);
            }
            xg_s[(lnl * 16 + j4 * 4 + 0) * 32 + lb] = xv.x;
            xg_s[(lnl * 16 + j4 * 4 + 1) * 32 + lb] = xv.y;
            xg_s[(lnl * 16 + j4 * 4 + 2) * 32 + lb] = xv.z;
            xg_s[(lnl * 16 + j4 * 4 + 3) * 32 + lb] = xv.w;
        }

        // --- stage theta chunk: theta_s[nl][kic][o] = sum_d emb * W ---
        // W index: (((t*E + d)*K + k)*CI + i)*CO + o
        const float* wbase = W + (((size_t)t * E_ * K_ + k) * CI_ + i0) * CO_;
#pragma unroll
        for (int r = 0; r < 32; r++) {
            const int ii  = tid + r * 256;
            const int nl  = ii >> 10;
            const int kic = (ii >> 6) & 15;
            const int o   = ii & 63;
            const float* wp = wbase + kic * CO_ + o;
            float v = 0.f;
#pragma unroll
            for (int d = 0; d < E_; d++)
                v = fmaf(emb_s[nl * E_ + d], wp[(size_t)d * K_ * CI_ * CO_], v);
            theta_s[ii] = v;
        }
        __syncthreads();

        // --- compute: acc[b][o] += xg[b][kic] * theta[kic][o] ---
#pragma unroll
        for (int kic = 0; kic < 16; kic++) {
            float4 xa = *(const float4*)&xg_s[(g * 16 + kic) * 32 + bq * 8];
            float4 xb = *(const float4*)&xg_s[(g * 16 + kic) * 32 + bq * 8 + 4];
            float4 ta = *(const float4*)&theta_s[(g * 16 + kic) * 64 + oq * 8];
            float4 tb = *(const float4*)&theta_s[(g * 16 + kic) * 64 + oq * 8 + 4];
            float xv[8] = {xa.x, xa.y, xa.z, xa.w, xb.x, xb.y, xb.z, xb.w};
            float tv[8] = {ta.x, ta.y, ta.z, ta.w, tb.x, tb.y, tb.z, tb.w};
#pragma unroll
            for (int i = 0; i < 8; i++)
#pragma unroll
                for (int j = 0; j < 8; j++) acc[i][j] = fmaf(xv[i], tv[j], acc[i][j]);
        }
    }

    // --- epilogue: relu(acc + bias) -> out[b,t,n,o] ---
    const int n = n0 + g;
#pragma unroll
    for (int bi = 0; bi < 8; bi++) {
        const int b = bq * 8 + bi;
        float* op = out + (((size_t)b * T_ + t) * N_ + n) * CO_ + oq * 8;
        float4 r0, r1;
        r0.x = fmaxf(acc[bi][0] + bias_s[g * 64 + oq * 8 + 0], 0.f);
        r0.y = fmaxf(acc[bi][1] + bias_s[g * 64 + oq * 8 + 1], 0.f);
        r0.z = fmaxf(acc[bi][2] + bias_s[g * 64 + oq * 8 + 2], 0.f);
        r0.w = fmaxf(acc[bi][3] + bias_s[g * 64 + oq * 8 + 3], 0.f);
        r1.x = fmaxf(acc[bi][4] + bias_s[g * 64 + oq * 8 + 4], 0.f);
        r1.y = fmaxf(acc[bi][5] + bias_s[g * 64 + oq * 8 + 5], 0.f);
        r1.z = fmaxf(acc[bi][6] + bias_s[g * 64 + oq * 8 + 6], 0.f);
        r1.w = fmaxf(acc[bi][7] + bias_s[g * 64 + oq * 8 + 7], 0.f);
        *(float4*)op       = r0;
        *(float4*)(op + 4) = r1;
    }
}

extern "C" void kernel_launch(void* const* d_in, const int* in_sizes, int n_in,
                              void* d_out, int out_size) {
    const float* x   = (const float*)d_in[0];  // [B,T,N,Ci]
    const float* emb = (const float*)d_in[1];  // [T,N,E]
    const float* W   = (const float*)d_in[2];  // [T,E,K,Ci,Co]
    const float* bp  = (const float*)d_in[3];  // [T,E,Co]
    float* out = (float*)d_out;                // [B,T,N,Co]

    cudaFuncSetAttribute(k_out, cudaFuncAttributeMaxDynamicSharedMemorySize,
                         SMEM_FLOATS * (int)sizeof(float));

    k_adj<<<dim3(N_, T_), 256>>>(emb);
    k_spmm<<<dim3(N_ / 128, B_ * T_), 256>>>(x);
    k_out<<<dim3(N_ / 8, T_), 256, SMEM_FLOATS * sizeof(float)>>>(x, emb, W, bp, out);
}

// round 7
// speedup vs baseline: 1.3321x; 1.3321x over previous
#include <cuda_runtime.h>
#include <cuda_bf16.h>
#include <cstdint>

#define B_  32
#define T_  12
#define N_  512
#define E_  10
#define K_  3
#define CI_ 64
#define CO_ 64

// Scratch (static device globals -- allocation-free per harness rules)
__device__ float         g_diag2[T_ * N_];                    // 2 * diag(A), fp32
__device__ __nv_bfloat16 g_Ah[(size_t)T_ * N_ * N_];          // A hi (bf16)
__device__ __nv_bfloat16 g_Al[(size_t)T_ * N_ * N_];          // A lo (bf16)
__device__ __nv_bfloat16 g_xh[(size_t)B_ * T_ * N_ * CI_];    // x hi
__device__ __nv_bfloat16 g_xl[(size_t)B_ * T_ * N_ * CI_];    // x lo
__device__ float         g_xg1[(size_t)B_ * T_ * N_ * CI_];   // A@x propagated (fp32)

// ---------------------------------------------------------------------------
// Kernel 1: adjacency. Warp-per-row; block = 8 rows, emb[t] loaded once.
// Emits bf16 hi/lo split of A plus fp32 2*diag(A).
// ---------------------------------------------------------------------------
__global__ void __launch_bounds__(256) k_adj(const float* __restrict__ emb) {
    const int t    = blockIdx.y;
    const int wid  = threadIdx.x >> 5;
    const int lane = threadIdx.x & 31;
    const int n    = blockIdx.x * 8 + wid;

    __shared__ float se[N_ * E_];
    const float* et = emb + (size_t)t * N_ * E_;
    for (int i = threadIdx.x; i < N_ * E_; i += 256) se[i] = et[i];
    __syncthreads();

    float en[E_];
#pragma unroll
    for (int e = 0; e < E_; e++) en[e] = se[n * E_ + e];

    float v[16];
#pragma unroll
    for (int q = 0; q < 16; q++) {
        const int m = lane + 32 * q;
        float s = 0.f;
#pragma unroll
        for (int e = 0; e < E_; e++) s = fmaf(en[e], se[m * E_ + e], s);
        v[q] = fmaxf(s, 0.f);
    }

    float mx = v[0];
#pragma unroll
    for (int q = 1; q < 16; q++) mx = fmaxf(mx, v[q]);
#pragma unroll
    for (int o = 16; o > 0; o >>= 1) mx = fmaxf(mx, __shfl_xor_sync(0xffffffffu, mx, o));

    float sum = 0.f;
#pragma unroll
    for (int q = 0; q < 16; q++) {
        v[q] = expf(v[q] - mx);
        sum += v[q];
    }
#pragma unroll
    for (int o = 16; o > 0; o >>= 1) sum += __shfl_xor_sync(0xffffffffu, sum, o);
    const float inv = 1.0f / sum;

    const size_t base = ((size_t)t * N_ + n) * N_;
#pragma unroll
    for (int q = 0; q < 16; q++) {
        const float p = v[q] * inv;
        const __nv_bfloat16 h = __float2bfloat16(p);
        const __nv_bfloat16 l = __float2bfloat16(p - __bfloat162float(h));
        g_Ah[base + lane + 32 * q] = h;
        g_Al[base + lane + 32 * q] = l;
        if (q == (n >> 5) && lane == (n & 31))
            g_diag2[t * N_ + n] = 2.0f * p;
    }
}

// ---------------------------------------------------------------------------
// Kernel 1b: split x into bf16 hi/lo. 4 elems/thread, exact-size grid.
// ---------------------------------------------------------------------------
__global__ void __launch_bounds__(256) k_split(const float* __restrict__ x) {
    const size_t i = ((size_t)blockIdx.x * 256 + threadIdx.x) * 4;
    const float4 vv = *(const float4*)(x + i);
    float f[4];
    f[0] = vv.x; f[1] = vv.y; f[2] = vv.z; f[3] = vv.w;
    __nv_bfloat16 h[4], l[4];
#pragma unroll
    for (int j = 0; j < 4; j++) {
        h[j] = __float2bfloat16(f[j]);
        l[j] = __float2bfloat16(f[j] - __bfloat162float(h[j]));
    }
    *((__nv_bfloat162*)(g_xh + i))     = __halves2bfloat162(h[0], h[1]);
    *((__nv_bfloat162*)(g_xh + i + 2)) = __halves2bfloat162(h[2], h[3]);
    *((__nv_bfloat162*)(g_xl + i))     = __halves2bfloat162(l[0], l[1]);
    *((__nv_bfloat162*)(g_xl + i + 2)) = __halves2bfloat162(l[2], l[3]);
}

// ---------------------------------------------------------------------------
// Kernel 2: xg1 = A @ x via mma.sync m16n8k16 bf16, 3-product split
// (AhXh + AlXh + AhXl) for near-fp32 accuracy. Per (b,t): M=512,N=64,K=512.
// Block tile 128x64, BK=32; 8 warps in 4(M)x2(N); warp tile 32x32.
// ---------------------------------------------------------------------------
#define SA 40   // Ah_s row stride (bf16): 32 + 8 pad  -> 80B, ldmatrix conflict-free
#define SX 72   // Xs row stride (bf16): 64 + 8 pad    -> 144B, conflict-free

__device__ __forceinline__ unsigned sptr(const void* p) {
    return (unsigned)__cvta_generic_to_shared(p);
}
__device__ __forceinline__ void ldsm4(unsigned* r, unsigned a) {
    asm volatile("ldmatrix.sync.aligned.m8n8.x4.shared.b16 {%0,%1,%2,%3}, [%4];"
                 : "=r"(r[0]), "=r"(r[1]), "=r"(r[2]), "=r"(r[3]) : "r"(a));
}
__device__ __forceinline__ void ldsm4t(unsigned* r, unsigned a) {
    asm volatile("ldmatrix.sync.aligned.m8n8.x4.trans.shared.b16 {%0,%1,%2,%3}, [%4];"
                 : "=r"(r[0]), "=r"(r[1]), "=r"(r[2]), "=r"(r[3]) : "r"(a));
}
__device__ __forceinline__ void mma16816(float* c, const unsigned* a, const unsigned* b) {
    asm volatile(
        "mma.sync.aligned.m16n8k16.row.col.f32.bf16.bf16.f32 "
        "{%0,%1,%2,%3}, {%4,%5,%6,%7}, {%8,%9}, {%0,%1,%2,%3};"
        : "+f"(c[0]), "+f"(c[1]), "+f"(c[2]), "+f"(c[3])
        : "r"(a[0]), "r"(a[1]), "r"(a[2]), "r"(a[3]), "r"(b[0]), "r"(b[1]));
}

__global__ void __launch_bounds__(256) k_spmm() {
    const int bt = blockIdx.y;             // b*T + t
    const int t  = bt % T_;
    const int n0 = blockIdx.x * 128;

    __shared__ __align__(16) __nv_bfloat16 Ah_s[128 * SA];
    __shared__ __align__(16) __nv_bfloat16 Al_s[128 * SA];
    __shared__ __align__(16) __nv_bfloat16 Xh_s[32 * SX];
    __shared__ __align__(16) __nv_bfloat16 Xl_s[32 * SX];

    const int tid  = threadIdx.x;
    const int lane = tid & 31;
    const int warp = tid >> 5;
    const int wm   = (warp & 3) * 32;      // warp M offset
    const int wn   = (warp >> 2) * 32;     // warp N offset

    // staging map
    const int rA = tid >> 1;               // A row 0..127
    const int qA = (tid & 1) * 16;         // bf16 col offset 0 or 16
    const int mX = tid >> 3;               // X row 0..31
    const int cX = (tid & 7) * 8;          // X col offset (8 bf16 = 1 uint4)

    const __nv_bfloat16* gAh = g_Ah + ((size_t)t * N_ + n0 + rA) * N_;
    const __nv_bfloat16* gAl = g_Al + ((size_t)t * N_ + n0 + rA) * N_;
    const __nv_bfloat16* gXh = g_xh + ((size_t)bt * N_ + mX) * CI_ + cX;
    const __nv_bfloat16* gXl = g_xl + ((size_t)bt * N_ + mX) * CI_ + cX;

    float acc[2][4][4];
#pragma unroll
    for (int i = 0; i < 2; i++)
#pragma unroll
        for (int j = 0; j < 4; j++)
#pragma unroll
            for (int r = 0; r < 4; r++) acc[i][j][r] = 0.f;

    // ldmatrix per-lane sub-tile offsets
    const int sub = lane >> 3;
    const int rl  = lane & 7;
    const int rAdd = ((sub & 1) << 3) + rl;   // row-in-tile
    const int cAdd = (sub >> 1) << 3;         // col-in-tile
    const unsigned baseAh = sptr(Ah_s);
    const unsigned baseAl = sptr(Al_s);
    const unsigned baseXh = sptr(Xh_s);
    const unsigned baseXl = sptr(Xl_s);

    uint4 pAh0, pAh1, pAl0, pAl1, pXh, pXl;

    // prologue: load + store chunk 0
    pAh0 = *(const uint4*)(gAh + qA);
    pAh1 = *(const uint4*)(gAh + qA + 8);
    pAl0 = *(const uint4*)(gAl + qA);
    pAl1 = *(const uint4*)(gAl + qA + 8);
    pXh  = *(const uint4*)(gXh);
    pXl  = *(const uint4*)(gXl);
    *(uint4*)&Ah_s[rA * SA + qA]     = pAh0;
    *(uint4*)&Ah_s[rA * SA + qA + 8] = pAh1;
    *(uint4*)&Al_s[rA * SA + qA]     = pAl0;
    *(uint4*)&Al_s[rA * SA + qA + 8] = pAl1;
    *(uint4*)&Xh_s[mX * SX + cX]     = pXh;
    *(uint4*)&Xl_s[mX * SX + cX]     = pXl;
    __syncthreads();

    for (int c = 0; c < 16; c++) {
        if (c < 15) {
            const int m0 = (c + 1) * 32;
            pAh0 = *(const uint4*)(gAh + m0 + qA);
            pAh1 = *(const uint4*)(gAh + m0 + qA + 8);
            pAl0 = *(const uint4*)(gAl + m0 + qA);
            pAl1 = *(const uint4*)(gAl + m0 + qA + 8);
            pXh  = *(const uint4*)(gXh + (size_t)m0 * CI_);
            pXl  = *(const uint4*)(gXl + (size_t)m0 * CI_);
        }

#pragma unroll
        for (int s = 0; s < 2; s++) {
            unsigned ah[2][4], al[2][4], bh[2][4], bl[2][4];
#pragma unroll
            for (int i = 0; i < 2; i++) {
                const unsigned off =
                    (unsigned)(((wm + i * 16 + rAdd) * SA + s * 16 + cAdd) * 2);
                ldsm4(ah[i], baseAh + off);
                ldsm4(al[i], baseAl + off);
            }
#pragma unroll
            for (int jp = 0; jp < 2; jp++) {
                const unsigned off =
                    (unsigned)(((s * 16 + rAdd) * SX + wn + jp * 16 + cAdd) * 2);
                ldsm4t(bh[jp], baseXh + off);
                ldsm4t(bl[jp], baseXl + off);
            }
#pragma unroll
            for (int i = 0; i < 2; i++)
#pragma unroll
                for (int j = 0; j < 4; j++) {
                    const unsigned* bH = &bh[j >> 1][(j & 1) * 2];
                    const unsigned* bL = &bl[j >> 1][(j & 1) * 2];
                    mma16816(acc[i][j], ah[i], bH);   // Ah*Xh
                    mma16816(acc[i][j], al[i], bH);   // Al*Xh
                    mma16816(acc[i][j], ah[i], bL);   // Ah*Xl
                }
        }

        __syncthreads();
        if (c < 15) {
            *(uint4*)&Ah_s[rA * SA + qA]     = pAh0;
            *(uint4*)&Ah_s[rA * SA + qA + 8] = pAh1;
            *(uint4*)&Al_s[rA * SA + qA]     = pAl0;
            *(uint4*)&Al_s[rA * SA + qA + 8] = pAl1;
            *(uint4*)&Xh_s[mX * SX + cX]     = pXh;
            *(uint4*)&Xl_s[mX * SX + cX]     = pXl;
        }
        __syncthreads();
    }

    float* obase = g_xg1 + (size_t)bt * N_ * CI_;
#pragma unroll
    for (int i = 0; i < 2; i++)
#pragma unroll
        for (int j = 0; j < 4; j++) {
            const int row = n0 + wm + i * 16 + (lane >> 2);
            const int col = wn + j * 8 + (lane & 3) * 2;
            float2 lo, hi;
            lo.x = acc[i][j][0]; lo.y = acc[i][j][1];
            hi.x = acc[i][j][2]; hi.y = acc[i][j][3];
            *(float2*)(obase + (size_t)row * CI_ + col)       = lo;
            *(float2*)(obase + (size_t)(row + 8) * CI_ + col) = hi;
        }
}

// ---------------------------------------------------------------------------
// Kernel 3: fused theta-generation + output contraction + bias + relu.
// (unchanged from baseline)
// ---------------------------------------------------------------------------
#define SMEM_FLOATS (8 * 16 * 64 + 8 * 16 * 32 + 8 * 64 + 96 + 8)

__global__ void __launch_bounds__(256) k_out(const float* __restrict__ x,
                                             const float* __restrict__ emb,
                                             const float* __restrict__ W,
                                             const float* __restrict__ bp,
                                             float* __restrict__ out) {
    extern __shared__ __align__(16) float sm[];
    float* theta_s = sm;                        // 8192
    float* xg_s    = sm + 8192;                 // 4096
    float* bias_s  = sm + 8192 + 4096;          // 512
    float* emb_s   = bias_s + 512;              // 80 (padded 96)
    float* d2_s    = emb_s + 96;                // 8

    const int t  = blockIdx.y;
    const int n0 = blockIdx.x * 8;
    const int tid = threadIdx.x;

    if (tid < 8 * E_)
        emb_s[tid] = emb[((size_t)t * N_ + n0 + tid / E_) * E_ + (tid % E_)];
    if (tid < 8) d2_s[tid] = g_diag2[t * N_ + n0 + tid];
    __syncthreads();

    for (int ii = tid; ii < 8 * CO_; ii += 256) {
        const int nl = ii >> 6;
        const int o  = ii & 63;
        float v = 0.f;
#pragma unroll
        for (int d = 0; d < E_; d++)
            v = fmaf(emb_s[nl * E_ + d], bp[((size_t)t * E_ + d) * CO_ + o], v);
        bias_s[ii] = v;
    }

    const int g  = tid >> 5;
    const int w  = tid & 31;
    const int bq = w >> 3;
    const int oq = w & 7;

    const int lnl = tid >> 5;
    const int lb  = tid & 31;
    const float* xrow  = x     + (((size_t)lb * T_ + t) * N_ + n0 + lnl) * CI_;
    const float* x1row = g_xg1 + (((size_t)lb * T_ + t) * N_ + n0 + lnl) * CI_;
    const float d2 = d2_s[lnl];

    float acc[8][8];
#pragma unroll
    for (int i = 0; i < 8; i++)
#pragma unroll
        for (int j = 0; j < 8; j++) acc[i][j] = 0.f;

    for (int c = 0; c < 12; c++) {
        const int k  = c >> 2;
        const int i0 = (c & 3) * 16;
        __syncthreads();

#pragma unroll
        for (int j4 = 0; j4 < 4; j4++) {
            float4 xv;
            if (k == 0) {
                xv = *(const float4*)(xrow + i0 + j4 * 4);
            } else if (k == 1) {
                xv = *(const float4*)(x1row + i0 + j4 * 4);
            } else {
                float4 a  = *(const float4*)(x1row + i0 + j4 * 4);
                float4 bb = *(const float4*)(xrow + i0 + j4 * 4);
                xv.x = fmaf(d2, a.x, -bb.x);
                xv.y = fmaf(d2, a.y, -bb.y);
                xv.z = fmaf(d2, a.z, -bb.z);
                xv.w = fmaf(d2, a.w, -bb.w);
            }
            xg_s[(lnl * 16 + j4 * 4 + 0) * 32 + lb] = xv.x;
            xg_s[(lnl * 16 + j4 * 4 + 1) * 32 + lb] = xv.y;
            xg_s[(lnl * 16 + j4 * 4 + 2) * 32 + lb] = xv.z;
            xg_s[(lnl * 16 + j4 * 4 + 3) * 32 + lb] = xv.w;
        }

        const float* wbase = W + (((size_t)t * E_ * K_ + k) * CI_ + i0) * CO_;
#pragma unroll
        for (int r = 0; r < 32; r++) {
            const int ii  = tid + r * 256;
            const int nl  = ii >> 10;
            const int kic = (ii >> 6) & 15;
            const int o   = ii & 63;
            const float* wp = wbase + kic * CO_ + o;
            float v = 0.f;
#pragma unroll
            for (int d = 0; d < E_; d++)
                v = fmaf(emb_s[nl * E_ + d], wp[(size_t)d * K_ * CI_ * CO_], v);
            theta_s[ii] = v;
        }
        __syncthreads();

#pragma unroll
        for (int kic = 0; kic < 16; kic++) {
            float4 xa = *(const float4*)&xg_s[(g * 16 + kic) * 32 + bq * 8];
            float4 xb = *(const float4*)&xg_s[(g * 16 + kic) * 32 + bq * 8 + 4];
            float4 ta = *(const float4*)&theta_s[(g * 16 + kic) * 64 + oq * 8];
            float4 tb = *(const float4*)&theta_s[(g * 16 + kic) * 64 + oq * 8 + 4];
            float xv[8], tv[8];
            xv[0] = xa.x; xv[1] = xa.y; xv[2] = xa.z; xv[3] = xa.w;
            xv[4] = xb.x; xv[5] = xb.y; xv[6] = xb.z; xv[7] = xb.w;
            tv[0] = ta.x; tv[1] = ta.y; tv[2] = ta.z; tv[3] = ta.w;
            tv[4] = tb.x; tv[5] = tb.y; tv[6] = tb.z; tv[7] = tb.w;
#pragma unroll
            for (int i = 0; i < 8; i++)
#pragma unroll
                for (int j = 0; j < 8; j++) acc[i][j] = fmaf(xv[i], tv[j], acc[i][j]);
        }
    }

    const int n = n0 + g;
#pragma unroll
    for (int bi = 0; bi < 8; bi++) {
        const int b = bq * 8 + bi;
        float* op = out + (((size_t)b * T_ + t) * N_ + n) * CO_ + oq * 8;
        float4 r0, r1;
        r0.x = fmaxf(acc[bi][0] + bias_s[g * 64 + oq * 8 + 0], 0.f);
        r0.y = fmaxf(acc[bi][1] + bias_s[g * 64 + oq * 8 + 1], 0.f);
        r0.z = fmaxf(acc[bi][2] + bias_s[g * 64 + oq * 8 + 2], 0.f);
        r0.w = fmaxf(acc[bi][3] + bias_s[g * 64 + oq * 8 + 3], 0.f);
        r1.x = fmaxf(acc[bi][4] + bias_s[g * 64 + oq * 8 + 4], 0.f);
        r1.y = fmaxf(acc[bi][5] + bias_s[g * 64 + oq * 8 + 5], 0.f);
        r1.z = fmaxf(acc[bi][6] + bias_s[g * 64 + oq * 8 + 6], 0.f);
        r1.w = fmaxf(acc[bi][7] + bias_s[g * 64 + oq * 8 + 7], 0.f);
        *(float4*)op       = r0;
        *(float4*)(op + 4) = r1;
    }
}

extern "C" void kernel_launch(void* const* d_in, const int* in_sizes, int n_in,
                              void* d_out, int out_size) {
    const float* x   = (const float*)d_in[0];  // [B,T,N,Ci]
    const float* emb = (const float*)d_in[1];  // [T,N,E]
    const float* W   = (const float*)d_in[2];  // [T,E,K,Ci,Co]
    const float* bp  = (const float*)d_in[3];  // [T,E,Co]
    float* out = (float*)d_out;                // [B,T,N,Co]

    cudaFuncSetAttribute(k_out, cudaFuncAttributeMaxDynamicSharedMemorySize,
                         SMEM_FLOATS * (int)sizeof(float));

    k_adj<<<dim3(N_ / 8, T_), 256>>>(emb);
    k_split<<<(B_ * T_ * N_ * CI_) / (256 * 4), 256>>>(x);
    k_spmm<<<dim3(N_ / 128, B_ * T_), 256>>>();
    k_out<<<dim3(N_ / 8, T_), 256, SMEM_FLOATS * sizeof(float)>>>(x, emb, W, bp, out);
}

// round 8
// speedup vs baseline: 1.3329x; 1.0006x over previous
#include <cuda_runtime.h>
#include <cuda_bf16.h>
#include <cstdint>

#define B_  32
#define T_  12
#define N_  512
#define E_  10
#define K_  3
#define CI_ 64
#define CO_ 64

// Scratch (static device globals -- allocation-free per harness rules)
__device__ float         g_diag2[T_ * N_];                    // 2 * diag(A), fp32
__device__ __nv_bfloat16 g_Ah[(size_t)T_ * N_ * N_];          // A hi (bf16)
__device__ __nv_bfloat16 g_Al[(size_t)T_ * N_ * N_];          // A lo (bf16)
__device__ __nv_bfloat16 g_xh[(size_t)B_ * T_ * N_ * CI_];    // x hi
__device__ __nv_bfloat16 g_xl[(size_t)B_ * T_ * N_ * CI_];    // x lo
__device__ float         g_xg1[(size_t)B_ * T_ * N_ * CI_];   // A@x propagated (fp32)

// ---------------------------------------------------------------------------
// Kernel 1: adjacency. Warp-per-row; block = 8 rows, emb[t] loaded once.
// Emits bf16 hi/lo split of A plus fp32 2*diag(A).
// ---------------------------------------------------------------------------
__global__ void __launch_bounds__(256) k_adj(const float* __restrict__ emb) {
    const int t    = blockIdx.y;
    const int wid  = threadIdx.x >> 5;
    const int lane = threadIdx.x & 31;
    const int n    = blockIdx.x * 8 + wid;

    __shared__ float se[N_ * E_];
    const float* et = emb + (size_t)t * N_ * E_;
    for (int i = threadIdx.x; i < N_ * E_; i += 256) se[i] = et[i];
    __syncthreads();

    float en[E_];
#pragma unroll
    for (int e = 0; e < E_; e++) en[e] = se[n * E_ + e];

    float v[16];
#pragma unroll
    for (int q = 0; q < 16; q++) {
        const int m = lane + 32 * q;
        float s = 0.f;
#pragma unroll
        for (int e = 0; e < E_; e++) s = fmaf(en[e], se[m * E_ + e], s);
        v[q] = fmaxf(s, 0.f);
    }

    float mx = v[0];
#pragma unroll
    for (int q = 1; q < 16; q++) mx = fmaxf(mx, v[q]);
#pragma unroll
    for (int o = 16; o > 0; o >>= 1) mx = fmaxf(mx, __shfl_xor_sync(0xffffffffu, mx, o));

    float sum = 0.f;
#pragma unroll
    for (int q = 0; q < 16; q++) {
        v[q] = expf(v[q] - mx);
        sum += v[q];
    }
#pragma unroll
    for (int o = 16; o > 0; o >>= 1) sum += __shfl_xor_sync(0xffffffffu, sum, o);
    const float inv = 1.0f / sum;

    const size_t base = ((size_t)t * N_ + n) * N_;
#pragma unroll
    for (int q = 0; q < 16; q++) {
        const float p = v[q] * inv;
        const __nv_bfloat16 h = __float2bfloat16(p);
        const __nv_bfloat16 l = __float2bfloat16(p - __bfloat162float(h));
        g_Ah[base + lane + 32 * q] = h;
        g_Al[base + lane + 32 * q] = l;
        if (q == (n >> 5) && lane == (n & 31))
            g_diag2[t * N_ + n] = 2.0f * p;
    }
}

// ---------------------------------------------------------------------------
// Kernel 1b: split x into bf16 hi/lo. 4 elems/thread, exact-size grid.
// ---------------------------------------------------------------------------
__global__ void __launch_bounds__(256) k_split(const float* __restrict__ x) {
    const size_t i = ((size_t)blockIdx.x * 256 + threadIdx.x) * 4;
    const float4 vv = *(const float4*)(x + i);
    float f[4];
    f[0] = vv.x; f[1] = vv.y; f[2] = vv.z; f[3] = vv.w;
    __nv_bfloat16 h[4], l[4];
#pragma unroll
    for (int j = 0; j < 4; j++) {
        h[j] = __float2bfloat16(f[j]);
        l[j] = __float2bfloat16(f[j] - __bfloat162float(h[j]));
    }
    *((__nv_bfloat162*)(g_xh + i))     = __halves2bfloat162(h[0], h[1]);
    *((__nv_bfloat162*)(g_xh + i + 2)) = __halves2bfloat162(h[2], h[3]);
    *((__nv_bfloat162*)(g_xl + i))     = __halves2bfloat162(l[0], l[1]);
    *((__nv_bfloat162*)(g_xl + i + 2)) = __halves2bfloat162(l[2], l[3]);
}

// ---------------------------------------------------------------------------
// Kernel 2: xg1 = A @ x via mma.sync m16n8k16 bf16, 3-product split
// (AhXh + AlXh + AhXl) for near-fp32 accuracy. Per (b,t): M=512,N=64,K=512.
// Block tile 128x64, BK=32; 8 warps in 4(M)x2(N); warp tile 32x32.
// ---------------------------------------------------------------------------
#define SA 40   // Ah_s row stride (bf16): 32 + 8 pad  -> 80B, ldmatrix conflict-free
#define SX 72   // Xs row stride (bf16): 64 + 8 pad    -> 144B, conflict-free

__device__ __forceinline__ unsigned sptr(const void* p) {
    return (unsigned)__cvta_generic_to_shared(p);
}
__device__ __forceinline__ void ldsm4(unsigned* r, unsigned a) {
    asm volatile("ldmatrix.sync.aligned.m8n8.x4.shared.b16 {%0,%1,%2,%3}, [%4];"
                 : "=r"(r[0]), "=r"(r[1]), "=r"(r[2]), "=r"(r[3]) : "r"(a));
}
__device__ __forceinline__ void ldsm4t(unsigned* r, unsigned a) {
    asm volatile("ldmatrix.sync.aligned.m8n8.x4.trans.shared.b16 {%0,%1,%2,%3}, [%4];"
                 : "=r"(r[0]), "=r"(r[1]), "=r"(r[2]), "=r"(r[3]) : "r"(a));
}
__device__ __forceinline__ void mma16816(float* c, const unsigned* a, const unsigned* b) {
    asm volatile(
        "mma.sync.aligned.m16n8k16.row.col.f32.bf16.bf16.f32 "
        "{%0,%1,%2,%3}, {%4,%5,%6,%7}, {%8,%9}, {%0,%1,%2,%3};"
        : "+f"(c[0]), "+f"(c[1]), "+f"(c[2]), "+f"(c[3])
        : "r"(a[0]), "r"(a[1]), "r"(a[2]), "r"(a[3]), "r"(b[0]), "r"(b[1]));
}

__global__ void __launch_bounds__(256) k_spmm() {
    const int bt = blockIdx.y;             // b*T + t
    const int t  = bt % T_;
    const int n0 = blockIdx.x * 128;

    __shared__ __align__(16) __nv_bfloat16 Ah_s[128 * SA];
    __shared__ __align__(16) __nv_bfloat16 Al_s[128 * SA];
    __shared__ __align__(16) __nv_bfloat16 Xh_s[32 * SX];
    __shared__ __align__(16) __nv_bfloat16 Xl_s[32 * SX];

    const int tid  = threadIdx.x;
    const int lane = tid & 31;
    const int warp = tid >> 5;
    const int wm   = (warp & 3) * 32;      // warp M offset
    const int wn   = (warp >> 2) * 32;     // warp N offset

    // staging map
    const int rA = tid >> 1;               // A row 0..127
    const int qA = (tid & 1) * 16;         // bf16 col offset 0 or 16
    const int mX = tid >> 3;               // X row 0..31
    const int cX = (tid & 7) * 8;          // X col offset (8 bf16 = 1 uint4)

    const __nv_bfloat16* gAh = g_Ah + ((size_t)t * N_ + n0 + rA) * N_;
    const __nv_bfloat16* gAl = g_Al + ((size_t)t * N_ + n0 + rA) * N_;
    const __nv_bfloat16* gXh = g_xh + ((size_t)bt * N_ + mX) * CI_ + cX;
    const __nv_bfloat16* gXl = g_xl + ((size_t)bt * N_ + mX) * CI_ + cX;

    float acc[2][4][4];
#pragma unroll
    for (int i = 0; i < 2; i++)
#pragma unroll
        for (int j = 0; j < 4; j++)
#pragma unroll
            for (int r = 0; r < 4; r++) acc[i][j][r] = 0.f;

    // ldmatrix per-lane sub-tile offsets
    const int sub = lane >> 3;
    const int rl  = lane & 7;
    const int rAdd = ((sub & 1) << 3) + rl;   // row-in-tile
    const int cAdd = (sub >> 1) << 3;         // col-in-tile
    const unsigned baseAh = sptr(Ah_s);
    const unsigned baseAl = sptr(Al_s);
    const unsigned baseXh = sptr(Xh_s);
    const unsigned baseXl = sptr(Xl_s);

    uint4 pAh0, pAh1, pAl0, pAl1, pXh, pXl;

    // prologue: load + store chunk 0
    pAh0 = *(const uint4*)(gAh + qA);
    pAh1 = *(const uint4*)(gAh + qA + 8);
    pAl0 = *(const uint4*)(gAl + qA);
    pAl1 = *(const uint4*)(gAl + qA + 8);
    pXh  = *(const uint4*)(gXh);
    pXl  = *(const uint4*)(gXl);
    *(uint4*)&Ah_s[rA * SA + qA]     = pAh0;
    *(uint4*)&Ah_s[rA * SA + qA + 8] = pAh1;
    *(uint4*)&Al_s[rA * SA + qA]     = pAl0;
    *(uint4*)&Al_s[rA * SA + qA + 8] = pAl1;
    *(uint4*)&Xh_s[mX * SX + cX]     = pXh;
    *(uint4*)&Xl_s[mX * SX + cX]     = pXl;
    __syncthreads();

    for (int c = 0; c < 16; c++) {
        if (c < 15) {
            const int m0 = (c + 1) * 32;
            pAh0 = *(const uint4*)(gAh + m0 + qA);
            pAh1 = *(const uint4*)(gAh + m0 + qA + 8);
            pAl0 = *(const uint4*)(gAl + m0 + qA);
            pAl1 = *(const uint4*)(gAl + m0 + qA + 8);
            pXh  = *(const uint4*)(gXh + (size_t)m0 * CI_);
            pXl  = *(const uint4*)(gXl + (size_t)m0 * CI_);
        }

#pragma unroll
        for (int s = 0; s < 2; s++) {
            unsigned ah[2][4], al[2][4], bh[2][4], bl[2][4];
#pragma unroll
            for (int i = 0; i < 2; i++) {
                const unsigned off =
                    (unsigned)(((wm + i * 16 + rAdd) * SA + s * 16 + cAdd) * 2);
                ldsm4(ah[i], baseAh + off);
                ldsm4(al[i], baseAl + off);
            }
#pragma unroll
            for (int jp = 0; jp < 2; jp++) {
                const unsigned off =
                    (unsigned)(((s * 16 + rAdd) * SX + wn + jp * 16 + cAdd) * 2);
                ldsm4t(bh[jp], baseXh + off);
                ldsm4t(bl[jp], baseXl + off);
            }
#pragma unroll
            for (int i = 0; i < 2; i++)
#pragma unroll
                for (int j = 0; j < 4; j++) {
                    const unsigned* bH = &bh[j >> 1][(j & 1) * 2];
                    const unsigned* bL = &bl[j >> 1][(j & 1) * 2];
                    mma16816(acc[i][j], ah[i], bH);   // Ah*Xh
                    mma16816(acc[i][j], al[i], bH);   // Al*Xh
                    mma16816(acc[i][j], ah[i], bL);   // Ah*Xl
                }
        }

        __syncthreads();
        if (c < 15) {
            *(uint4*)&Ah_s[rA * SA + qA]     = pAh0;
            *(uint4*)&Ah_s[rA * SA + qA + 8] = pAh1;
            *(uint4*)&Al_s[rA * SA + qA]     = pAl0;
            *(uint4*)&Al_s[rA * SA + qA + 8] = pAl1;
            *(uint4*)&Xh_s[mX * SX + cX]     = pXh;
            *(uint4*)&Xl_s[mX * SX + cX]     = pXl;
        }
        __syncthreads();
    }

    float* obase = g_xg1 + (size_t)bt * N_ * CI_;
#pragma unroll
    for (int i = 0; i < 2; i++)
#pragma unroll
        for (int j = 0; j < 4; j++) {
            const int row = n0 + wm + i * 16 + (lane >> 2);
            const int col = wn + j * 8 + (lane & 3) * 2;
            float2 lo, hi;
            lo.x = acc[i][j][0]; lo.y = acc[i][j][1];
            hi.x = acc[i][j][2]; hi.y = acc[i][j][3];
            *(float2*)(obase + (size_t)row * CI_ + col)       = lo;
            *(float2*)(obase + (size_t)(row + 8) * CI_ + col) = hi;
        }
}

// ---------------------------------------------------------------------------
// Kernel 3: fused theta-generation + output contraction + bias + relu.
// theta-gen is register-blocked over the 8 nodes: each thread owns 4 (kic,o)
// slots and accumulates all 8 nodes' theta in registers -> 8x fewer W loads.
// ---------------------------------------------------------------------------
#define SMEM_FLOATS (8 * 16 * 64 + 8 * 16 * 32 + 8 * 64 + 96 + 8)

__global__ void __launch_bounds__(256) k_out(const float* __restrict__ x,
                                             const float* __restrict__ emb,
                                             const float* __restrict__ W,
                                             const float* __restrict__ bp,
                                             float* __restrict__ out) {
    extern __shared__ __align__(16) float sm[];
    float* theta_s = sm;                        // 8192
    float* xg_s    = sm + 8192;                 // 4096
    float* bias_s  = sm + 8192 + 4096;          // 512
    float* emb_s   = bias_s + 512;              // 80 (padded 96)
    float* d2_s    = emb_s + 96;                // 8

    const int t  = blockIdx.y;
    const int n0 = blockIdx.x * 8;
    const int tid = threadIdx.x;

    if (tid < 8 * E_)
        emb_s[tid] = emb[((size_t)t * N_ + n0 + tid / E_) * E_ + (tid % E_)];
    if (tid < 8) d2_s[tid] = g_diag2[t * N_ + n0 + tid];
    __syncthreads();

    for (int ii = tid; ii < 8 * CO_; ii += 256) {
        const int nl = ii >> 6;
        const int o  = ii & 63;
        float v = 0.f;
#pragma unroll
        for (int d = 0; d < E_; d++)
            v = fmaf(emb_s[nl * E_ + d], bp[((size_t)t * E_ + d) * CO_ + o], v);
        bias_s[ii] = v;
    }

    const int g  = tid >> 5;
    const int w  = tid & 31;
    const int bq = w >> 3;
    const int oq = w & 7;

    const int lnl = tid >> 5;
    const int lb  = tid & 31;
    const float* xrow  = x     + (((size_t)lb * T_ + t) * N_ + n0 + lnl) * CI_;
    const float* x1row = g_xg1 + (((size_t)lb * T_ + t) * N_ + n0 + lnl) * CI_;
    const float d2 = d2_s[lnl];

    // theta-gen slot for this thread: 4 slots of (kic, o), stride 256
    const int kic0 = tid >> 6;          // slot r: kic = kic0 + r*4
    const int oo   = tid & 63;

    float acc[8][8];
#pragma unroll
    for (int i = 0; i < 8; i++)
#pragma unroll
        for (int j = 0; j < 8; j++) acc[i][j] = 0.f;

    for (int c = 0; c < 12; c++) {
        const int k  = c >> 2;
        const int i0 = (c & 3) * 16;
        __syncthreads();

        // --- stage xg chunk: xg_s[nl][kic][b] ---
#pragma unroll
        for (int j4 = 0; j4 < 4; j4++) {
            float4 xv;
            if (k == 0) {
                xv = *(const float4*)(xrow + i0 + j4 * 4);
            } else if (k == 1) {
                xv = *(const float4*)(x1row + i0 + j4 * 4);
            } else {
                float4 a  = *(const float4*)(x1row + i0 + j4 * 4);
                float4 bb = *(const float4*)(xrow + i0 + j4 * 4);
                xv.x = fmaf(d2, a.x, -bb.x);
                xv.y = fmaf(d2, a.y, -bb.y);
                xv.z = fmaf(d2, a.z, -bb.z);
                xv.w = fmaf(d2, a.w, -bb.w);
            }
            xg_s[(lnl * 16 + j4 * 4 + 0) * 32 + lb] = xv.x;
            xg_s[(lnl * 16 + j4 * 4 + 1) * 32 + lb] = xv.y;
            xg_s[(lnl * 16 + j4 * 4 + 2) * 32 + lb] = xv.z;
            xg_s[(lnl * 16 + j4 * 4 + 3) * 32 + lb] = xv.w;
        }

        // --- theta-gen, register-blocked over the 8 nodes ---
        // W index: (((t*E + d)*K + k)*CI + i)*CO + o ; d-stride = K*CI*CO
        const float* wbase = W + (((size_t)t * E_ * K_ + k) * CI_ + i0) * CO_;
#pragma unroll 1
        for (int r = 0; r < 4; r++) {
            const int kic = kic0 + r * 4;
            const float* wp = wbase + kic * CO_ + oo;
            float th0 = 0.f, th1 = 0.f, th2 = 0.f, th3 = 0.f;
            float th4 = 0.f, th5 = 0.f, th6 = 0.f, th7 = 0.f;
#pragma unroll
            for (int d = 0; d < E_; d++) {
                const float wv = wp[(size_t)d * (K_ * CI_ * CO_)];
                th0 = fmaf(emb_s[0 * E_ + d], wv, th0);
                th1 = fmaf(emb_s[1 * E_ + d], wv, th1);
                th2 = fmaf(emb_s[2 * E_ + d], wv, th2);
                th3 = fmaf(emb_s[3 * E_ + d], wv, th3);
                th4 = fmaf(emb_s[4 * E_ + d], wv, th4);
                th5 = fmaf(emb_s[5 * E_ + d], wv, th5);
                th6 = fmaf(emb_s[6 * E_ + d], wv, th6);
                th7 = fmaf(emb_s[7 * E_ + d], wv, th7);
            }
            theta_s[(0 * 16 + kic) * 64 + oo] = th0;
            theta_s[(1 * 16 + kic) * 64 + oo] = th1;
            theta_s[(2 * 16 + kic) * 64 + oo] = th2;
            theta_s[(3 * 16 + kic) * 64 + oo] = th3;
            theta_s[(4 * 16 + kic) * 64 + oo] = th4;
            theta_s[(5 * 16 + kic) * 64 + oo] = th5;
            theta_s[(6 * 16 + kic) * 64 + oo] = th6;
            theta_s[(7 * 16 + kic) * 64 + oo] = th7;
        }
        __syncthreads();

        // --- compute: acc[b][o] += xg[b][kic] * theta[kic][o] ---
#pragma unroll
        for (int kic = 0; kic < 16; kic++) {
            float4 xa = *(const float4*)&xg_s[(g * 16 + kic) * 32 + bq * 8];
            float4 xb = *(const float4*)&xg_s[(g * 16 + kic) * 32 + bq * 8 + 4];
            float4 ta = *(const float4*)&theta_s[(g * 16 + kic) * 64 + oq * 8];
            float4 tb = *(const float4*)&theta_s[(g * 16 + kic) * 64 + oq * 8 + 4];
            float xv[8], tv[8];
            xv[0] = xa.x; xv[1] = xa.y; xv[2] = xa.z; xv[3] = xa.w;
            xv[4] = xb.x; xv[5] = xb.y; xv[6] = xb.z; xv[7] = xb.w;
            tv[0] = ta.x; tv[1] = ta.y; tv[2] = ta.z; tv[3] = ta.w;
            tv[4] = tb.x; tv[5] = tb.y; tv[6] = tb.z; tv[7] = tb.w;
#pragma unroll
            for (int i = 0; i < 8; i++)
#pragma unroll
                for (int j = 0; j < 8; j++) acc[i][j] = fmaf(xv[i], tv[j], acc[i][j]);
        }
    }

    const int n = n0 + g;
#pragma unroll
    for (int bi = 0; bi < 8; bi++) {
        const int b = bq * 8 + bi;
        float* op = out + (((size_t)b * T_ + t) * N_ + n) * CO_ + oq * 8;
        float4 r0, r1;
        r0.x = fmaxf(acc[bi][0] + bias_s[g * 64 + oq * 8 + 0], 0.f);
        r0.y = fmaxf(acc[bi][1] + bias_s[g * 64 + oq * 8 + 1], 0.f);
        r0.z = fmaxf(acc[bi][2] + bias_s[g * 64 + oq * 8 + 2], 0.f);
        r0.w = fmaxf(acc[bi][3] + bias_s[g * 64 + oq * 8 + 3], 0.f);
        r1.x = fmaxf(acc[bi][4] + bias_s[g * 64 + oq * 8 + 4], 0.f);
        r1.y = fmaxf(acc[bi][5] + bias_s[g * 64 + oq * 8 + 5], 0.f);
        r1.z = fmaxf(acc[bi][6] + bias_s[g * 64 + oq * 8 + 6], 0.f);
        r1.w = fmaxf(acc[bi][7] + bias_s[g * 64 + oq * 8 + 7], 0.f);
        *(float4*)op       = r0;
        *(float4*)(op + 4) = r1;
    }
}

extern "C" void kernel_launch(void* const* d_in, const int* in_sizes, int n_in,
                              void* d_out, int out_size) {
    const float* x   = (const float*)d_in[0];  // [B,T,N,Ci]
    const float* emb = (const float*)d_in[1];  // [T,N,E]
    const float* W   = (const float*)d_in[2];  // [T,E,K,Ci,Co]
    const float* bp  = (const float*)d_in[3];  // [T,E,Co]
    float* out = (float*)d_out;                // [B,T,N,Co]

    cudaFuncSetAttribute(k_out, cudaFuncAttributeMaxDynamicSharedMemorySize,
                         SMEM_FLOATS * (int)sizeof(float));

    k_adj<<<dim3(N_ / 8, T_), 256>>>(emb);
    k_split<<<(B_ * T_ * N_ * CI_) / (256 * 4), 256>>>(x);
    k_spmm<<<dim3(N_ / 128, B_ * T_), 256>>>();
    k_out<<<dim3(N_ / 8, T_), 256, SMEM_FLOATS * sizeof(float)>>>(x, emb, W, bp, out);
}

// round 9
// speedup vs baseline: 1.4697x; 1.1026x over previous
#include <cuda_runtime.h>
#include <cuda_bf16.h>
#include <cstdint>

#define B_  32
#define T_  12
#define N_  512
#define E_  10
#define K_  3
#define CI_ 64
#define CO_ 64

// Scratch (static device globals -- allocation-free per harness rules)
__device__ float         g_diag2[T_ * N_];                    // 2 * diag(A), fp32
__device__ __nv_bfloat16 g_Ah[(size_t)T_ * N_ * N_];          // A hi (bf16)
__device__ __nv_bfloat16 g_Al[(size_t)T_ * N_ * N_];          // A lo (bf16)
__device__ __nv_bfloat16 g_xh[(size_t)B_ * T_ * N_ * CI_];    // x hi
__device__ __nv_bfloat16 g_xl[(size_t)B_ * T_ * N_ * CI_];    // x lo
__device__ float         g_xg1[(size_t)B_ * T_ * N_ * CI_];   // A@x propagated (fp32)

// ---------------------------------------------------------------------------
// Kernel 1: adjacency. Warp-per-row; block = 8 rows, emb[t] loaded once.
// Emits bf16 hi/lo split of A plus fp32 2*diag(A).
// ---------------------------------------------------------------------------
__global__ void __launch_bounds__(256) k_adj(const float* __restrict__ emb) {
    const int t    = blockIdx.y;
    const int wid  = threadIdx.x >> 5;
    const int lane = threadIdx.x & 31;
    const int n    = blockIdx.x * 8 + wid;

    __shared__ float se[N_ * E_];
    const float* et = emb + (size_t)t * N_ * E_;
    for (int i = threadIdx.x; i < N_ * E_; i += 256) se[i] = et[i];
    __syncthreads();

    float en[E_];
#pragma unroll
    for (int e = 0; e < E_; e++) en[e] = se[n * E_ + e];

    float v[16];
#pragma unroll
    for (int q = 0; q < 16; q++) {
        const int m = lane + 32 * q;
        float s = 0.f;
#pragma unroll
        for (int e = 0; e < E_; e++) s = fmaf(en[e], se[m * E_ + e], s);
        v[q] = fmaxf(s, 0.f);
    }

    float mx = v[0];
#pragma unroll
    for (int q = 1; q < 16; q++) mx = fmaxf(mx, v[q]);
#pragma unroll
    for (int o = 16; o > 0; o >>= 1) mx = fmaxf(mx, __shfl_xor_sync(0xffffffffu, mx, o));

    float sum = 0.f;
#pragma unroll
    for (int q = 0; q < 16; q++) {
        v[q] = expf(v[q] - mx);
        sum += v[q];
    }
#pragma unroll
    for (int o = 16; o > 0; o >>= 1) sum += __shfl_xor_sync(0xffffffffu, sum, o);
    const float inv = 1.0f / sum;

    const size_t base = ((size_t)t * N_ + n) * N_;
#pragma unroll
    for (int q = 0; q < 16; q++) {
        const float p = v[q] * inv;
        const __nv_bfloat16 h = __float2bfloat16(p);
        const __nv_bfloat16 l = __float2bfloat16(p - __bfloat162float(h));
        g_Ah[base + lane + 32 * q] = h;
        g_Al[base + lane + 32 * q] = l;
        if (q == (n >> 5) && lane == (n & 31))
            g_diag2[t * N_ + n] = 2.0f * p;
    }
}

// ---------------------------------------------------------------------------
// Kernel 1b: split x into bf16 hi/lo. 4 elems/thread, exact-size grid.
// ---------------------------------------------------------------------------
__global__ void __launch_bounds__(256) k_split(const float* __restrict__ x) {
    const size_t i = ((size_t)blockIdx.x * 256 + threadIdx.x) * 4;
    const float4 vv = *(const float4*)(x + i);
    float f[4];
    f[0] = vv.x; f[1] = vv.y; f[2] = vv.z; f[3] = vv.w;
    __nv_bfloat16 h[4], l[4];
#pragma unroll
    for (int j = 0; j < 4; j++) {
        h[j] = __float2bfloat16(f[j]);
        l[j] = __float2bfloat16(f[j] - __bfloat162float(h[j]));
    }
    *((__nv_bfloat162*)(g_xh + i))     = __halves2bfloat162(h[0], h[1]);
    *((__nv_bfloat162*)(g_xh + i + 2)) = __halves2bfloat162(h[2], h[3]);
    *((__nv_bfloat162*)(g_xl + i))     = __halves2bfloat162(l[0], l[1]);
    *((__nv_bfloat162*)(g_xl + i + 2)) = __halves2bfloat162(l[2], l[3]);
}

// ---------------------------------------------------------------------------
// Kernel 2: xg1 = A @ x via mma.sync m16n8k16 bf16, 3-product split
// (AhXh + AlXh + AhXl) for near-fp32 accuracy. Per (b,t): M=512,N=64,K=512.
// Block tile 128x64, BK=32; 8 warps in 4(M)x2(N); warp tile 32x32.
// ---------------------------------------------------------------------------
#define SA 40   // Ah_s row stride (bf16): 32 + 8 pad  -> 80B, ldmatrix conflict-free
#define SX 72   // Xs row stride (bf16): 64 + 8 pad    -> 144B, conflict-free

__device__ __forceinline__ unsigned sptr(const void* p) {
    return (unsigned)__cvta_generic_to_shared(p);
}
__device__ __forceinline__ void ldsm4(unsigned* r, unsigned a) {
    asm volatile("ldmatrix.sync.aligned.m8n8.x4.shared.b16 {%0,%1,%2,%3}, [%4];"
                 : "=r"(r[0]), "=r"(r[1]), "=r"(r[2]), "=r"(r[3]) : "r"(a));
}
__device__ __forceinline__ void ldsm4t(unsigned* r, unsigned a) {
    asm volatile("ldmatrix.sync.aligned.m8n8.x4.trans.shared.b16 {%0,%1,%2,%3}, [%4];"
                 : "=r"(r[0]), "=r"(r[1]), "=r"(r[2]), "=r"(r[3]) : "r"(a));
}
__device__ __forceinline__ void mma16816(float* c, const unsigned* a, const unsigned* b) {
    asm volatile(
        "mma.sync.aligned.m16n8k16.row.col.f32.bf16.bf16.f32 "
        "{%0,%1,%2,%3}, {%4,%5,%6,%7}, {%8,%9}, {%0,%1,%2,%3};"
        : "+f"(c[0]), "+f"(c[1]), "+f"(c[2]), "+f"(c[3])
        : "r"(a[0]), "r"(a[1]), "r"(a[2]), "r"(a[3]), "r"(b[0]), "r"(b[1]));
}

__global__ void __launch_bounds__(256) k_spmm() {
    const int bt = blockIdx.y;             // b*T + t
    const int t  = bt % T_;
    const int n0 = blockIdx.x * 128;

    __shared__ __align__(16) __nv_bfloat16 Ah_s[128 * SA];
    __shared__ __align__(16) __nv_bfloat16 Al_s[128 * SA];
    __shared__ __align__(16) __nv_bfloat16 Xh_s[32 * SX];
    __shared__ __align__(16) __nv_bfloat16 Xl_s[32 * SX];

    const int tid  = threadIdx.x;
    const int lane = tid & 31;
    const int warp = tid >> 5;
    const int wm   = (warp & 3) * 32;      // warp M offset
    const int wn   = (warp >> 2) * 32;     // warp N offset

    // staging map
    const int rA = tid >> 1;               // A row 0..127
    const int qA = (tid & 1) * 16;         // bf16 col offset 0 or 16
    const int mX = tid >> 3;               // X row 0..31
    const int cX = (tid & 7) * 8;          // X col offset (8 bf16 = 1 uint4)

    const __nv_bfloat16* gAh = g_Ah + ((size_t)t * N_ + n0 + rA) * N_;
    const __nv_bfloat16* gAl = g_Al + ((size_t)t * N_ + n0 + rA) * N_;
    const __nv_bfloat16* gXh = g_xh + ((size_t)bt * N_ + mX) * CI_ + cX;
    const __nv_bfloat16* gXl = g_xl + ((size_t)bt * N_ + mX) * CI_ + cX;

    float acc[2][4][4];
#pragma unroll
    for (int i = 0; i < 2; i++)
#pragma unroll
        for (int j = 0; j < 4; j++)
#pragma unroll
            for (int r = 0; r < 4; r++) acc[i][j][r] = 0.f;

    // ldmatrix per-lane sub-tile offsets
    const int sub = lane >> 3;
    const int rl  = lane & 7;
    const int rAdd = ((sub & 1) << 3) + rl;   // row-in-tile
    const int cAdd = (sub >> 1) << 3;         // col-in-tile
    const unsigned baseAh = sptr(Ah_s);
    const unsigned baseAl = sptr(Al_s);
    const unsigned baseXh = sptr(Xh_s);
    const unsigned baseXl = sptr(Xl_s);

    uint4 pAh0, pAh1, pAl0, pAl1, pXh, pXl;

    // prologue: load + store chunk 0
    pAh0 = *(const uint4*)(gAh + qA);
    pAh1 = *(const uint4*)(gAh + qA + 8);
    pAl0 = *(const uint4*)(gAl + qA);
    pAl1 = *(const uint4*)(gAl + qA + 8);
    pXh  = *(const uint4*)(gXh);
    pXl  = *(const uint4*)(gXl);
    *(uint4*)&Ah_s[rA * SA + qA]     = pAh0;
    *(uint4*)&Ah_s[rA * SA + qA + 8] = pAh1;
    *(uint4*)&Al_s[rA * SA + qA]     = pAl0;
    *(uint4*)&Al_s[rA * SA + qA + 8] = pAl1;
    *(uint4*)&Xh_s[mX * SX + cX]     = pXh;
    *(uint4*)&Xl_s[mX * SX + cX]     = pXl;
    __syncthreads();

    for (int c = 0; c < 16; c++) {
        if (c < 15) {
            const int m0 = (c + 1) * 32;
            pAh0 = *(const uint4*)(gAh + m0 + qA);
            pAh1 = *(const uint4*)(gAh + m0 + qA + 8);
            pAl0 = *(const uint4*)(gAl + m0 + qA);
            pAl1 = *(const uint4*)(gAl + m0 + qA + 8);
            pXh  = *(const uint4*)(gXh + (size_t)m0 * CI_);
            pXl  = *(const uint4*)(gXl + (size_t)m0 * CI_);
        }

#pragma unroll
        for (int s = 0; s < 2; s++) {
            unsigned ah[2][4], al[2][4], bh[2][4], bl[2][4];
#pragma unroll
            for (int i = 0; i < 2; i++) {
                const unsigned off =
                    (unsigned)(((wm + i * 16 + rAdd) * SA + s * 16 + cAdd) * 2);
                ldsm4(ah[i], baseAh + off);
                ldsm4(al[i], baseAl + off);
            }
#pragma unroll
            for (int jp = 0; jp < 2; jp++) {
                const unsigned off =
                    (unsigned)(((s * 16 + rAdd) * SX + wn + jp * 16 + cAdd) * 2);
                ldsm4t(bh[jp], baseXh + off);
                ldsm4t(bl[jp], baseXl + off);
            }
#pragma unroll
            for (int i = 0; i < 2; i++)
#pragma unroll
                for (int j = 0; j < 4; j++) {
                    const unsigned* bH = &bh[j >> 1][(j & 1) * 2];
                    const unsigned* bL = &bl[j >> 1][(j & 1) * 2];
                    mma16816(acc[i][j], ah[i], bH);   // Ah*Xh
                    mma16816(acc[i][j], al[i], bH);   // Al*Xh
                    mma16816(acc[i][j], ah[i], bL);   // Ah*Xl
                }
        }

        __syncthreads();
        if (c < 15) {
            *(uint4*)&Ah_s[rA * SA + qA]     = pAh0;
            *(uint4*)&Ah_s[rA * SA + qA + 8] = pAh1;
            *(uint4*)&Al_s[rA * SA + qA]     = pAl0;
            *(uint4*)&Al_s[rA * SA + qA + 8] = pAl1;
            *(uint4*)&Xh_s[mX * SX + cX]     = pXh;
            *(uint4*)&Xl_s[mX * SX + cX]     = pXl;
        }
        __syncthreads();
    }

    float* obase = g_xg1 + (size_t)bt * N_ * CI_;
#pragma unroll
    for (int i = 0; i < 2; i++)
#pragma unroll
        for (int j = 0; j < 4; j++) {
            const int row = n0 + wm + i * 16 + (lane >> 2);
            const int col = wn + j * 8 + (lane & 3) * 2;
            float2 lo, hi;
            lo.x = acc[i][j][0]; lo.y = acc[i][j][1];
            hi.x = acc[i][j][2]; hi.y = acc[i][j][3];
            *(float2*)(obase + (size_t)row * CI_ + col)       = lo;
            *(float2*)(obase + (size_t)(row + 8) * CI_ + col) = hi;
        }
}

// ---------------------------------------------------------------------------
// Kernel 3: fused theta-generation + output contraction + bias + relu.
// theta-gen register-blocked over nodes (8x fewer W loads).
// __launch_bounds__(256, 2): cap regs at 128 so 2 blocks/SM co-reside --
// round-8 profile showed occ=12.5% (1 block/SM @ 134 regs) as the binding
// constraint (issue=35%, fma=26%, all memory %s low).
// ---------------------------------------------------------------------------
#define SMEM_FLOATS (8 * 16 * 64 + 8 * 16 * 32 + 8 * 64 + 96 + 8)

__global__ void __launch_bounds__(256, 2) k_out(const float* __restrict__ x,
                                                const float* __restrict__ emb,
                                                const float* __restrict__ W,
                                                const float* __restrict__ bp,
                                                float* __restrict__ out) {
    extern __shared__ __align__(16) float sm[];
    float* theta_s = sm;                        // 8192
    float* xg_s    = sm + 8192;                 // 4096
    float* bias_s  = sm + 8192 + 4096;          // 512
    float* emb_s   = bias_s + 512;              // 80 (padded 96)
    float* d2_s    = emb_s + 96;                // 8

    const int t  = blockIdx.y;
    const int n0 = blockIdx.x * 8;
    const int tid = threadIdx.x;

    if (tid < 8 * E_)
        emb_s[tid] = emb[((size_t)t * N_ + n0 + tid / E_) * E_ + (tid % E_)];
    if (tid < 8) d2_s[tid] = g_diag2[t * N_ + n0 + tid];
    __syncthreads();

    for (int ii = tid; ii < 8 * CO_; ii += 256) {
        const int nl = ii >> 6;
        const int o  = ii & 63;
        float v = 0.f;
#pragma unroll
        for (int d = 0; d < E_; d++)
            v = fmaf(emb_s[nl * E_ + d], bp[((size_t)t * E_ + d) * CO_ + o], v);
        bias_s[ii] = v;
    }

    const int g  = tid >> 5;
    const int w  = tid & 31;
    const int bq = w >> 3;
    const int oq = w & 7;

    const int lnl = tid >> 5;
    const int lb  = tid & 31;
    const float* xrow  = x     + (((size_t)lb * T_ + t) * N_ + n0 + lnl) * CI_;
    const float* x1row = g_xg1 + (((size_t)lb * T_ + t) * N_ + n0 + lnl) * CI_;
    const float d2 = d2_s[lnl];

    // theta-gen slot for this thread: 4 slots of (kic, o), stride 256
    const int kic0 = tid >> 6;          // slot r: kic = kic0 + r*4
    const int oo   = tid & 63;

    float acc[8][8];
#pragma unroll
    for (int i = 0; i < 8; i++)
#pragma unroll
        for (int j = 0; j < 8; j++) acc[i][j] = 0.f;

    for (int c = 0; c < 12; c++) {
        const int k  = c >> 2;
        const int i0 = (c & 3) * 16;
        __syncthreads();

        // --- stage xg chunk: xg_s[nl][kic][b] ---
#pragma unroll
        for (int j4 = 0; j4 < 4; j4++) {
            float4 xv;
            if (k == 0) {
                xv = *(const float4*)(xrow + i0 + j4 * 4);
            } else if (k == 1) {
                xv = *(const float4*)(x1row + i0 + j4 * 4);
            } else {
                float4 a  = *(const float4*)(x1row + i0 + j4 * 4);
                float4 bb = *(const float4*)(xrow + i0 + j4 * 4);
                xv.x = fmaf(d2, a.x, -bb.x);
                xv.y = fmaf(d2, a.y, -bb.y);
                xv.z = fmaf(d2, a.z, -bb.z);
                xv.w = fmaf(d2, a.w, -bb.w);
            }
            xg_s[(lnl * 16 + j4 * 4 + 0) * 32 + lb] = xv.x;
            xg_s[(lnl * 16 + j4 * 4 + 1) * 32 + lb] = xv.y;
            xg_s[(lnl * 16 + j4 * 4 + 2) * 32 + lb] = xv.z;
            xg_s[(lnl * 16 + j4 * 4 + 3) * 32 + lb] = xv.w;
        }

        // --- theta-gen, register-blocked over the 8 nodes ---
        // W index: (((t*E + d)*K + k)*CI + i)*CO + o ; d-stride = K*CI*CO
        const float* wbase = W + (((size_t)t * E_ * K_ + k) * CI_ + i0) * CO_;
#pragma unroll 1
        for (int r = 0; r < 4; r++) {
            const int kic = kic0 + r * 4;
            const float* wp = wbase + kic * CO_ + oo;
            float th0 = 0.f, th1 = 0.f, th2 = 0.f, th3 = 0.f;
            float th4 = 0.f, th5 = 0.f, th6 = 0.f, th7 = 0.f;
#pragma unroll
            for (int d = 0; d < E_; d++) {
                const float wv = wp[(size_t)d * (K_ * CI_ * CO_)];
                th0 = fmaf(emb_s[0 * E_ + d], wv, th0);
                th1 = fmaf(emb_s[1 * E_ + d], wv, th1);
                th2 = fmaf(emb_s[2 * E_ + d], wv, th2);
                th3 = fmaf(emb_s[3 * E_ + d], wv, th3);
                th4 = fmaf(emb_s[4 * E_ + d], wv, th4);
                th5 = fmaf(emb_s[5 * E_ + d], wv, th5);
                th6 = fmaf(emb_s[6 * E_ + d], wv, th6);
                th7 = fmaf(emb_s[7 * E_ + d], wv, th7);
            }
            theta_s[(0 * 16 + kic) * 64 + oo] = th0;
            theta_s[(1 * 16 + kic) * 64 + oo] = th1;
            theta_s[(2 * 16 + kic) * 64 + oo] = th2;
            theta_s[(3 * 16 + kic) * 64 + oo] = th3;
            theta_s[(4 * 16 + kic) * 64 + oo] = th4;
            theta_s[(5 * 16 + kic) * 64 + oo] = th5;
            theta_s[(6 * 16 + kic) * 64 + oo] = th6;
            theta_s[(7 * 16 + kic) * 64 + oo] = th7;
        }
        __syncthreads();

        // --- compute: acc[b][o] += xg[b][kic] * theta[kic][o] ---
#pragma unroll
        for (int kic = 0; kic < 16; kic++) {
            float4 xa = *(const float4*)&xg_s[(g * 16 + kic) * 32 + bq * 8];
            float4 xb = *(const float4*)&xg_s[(g * 16 + kic) * 32 + bq * 8 + 4];
            float4 ta = *(const float4*)&theta_s[(g * 16 + kic) * 64 + oq * 8];
            float4 tb = *(const float4*)&theta_s[(g * 16 + kic) * 64 + oq * 8 + 4];
            float xv[8], tv[8];
            xv[0] = xa.x; xv[1] = xa.y; xv[2] = xa.z; xv[3] = xa.w;
            xv[4] = xb.x; xv[5] = xb.y; xv[6] = xb.z; xv[7] = xb.w;
            tv[0] = ta.x; tv[1] = ta.y; tv[2] = ta.z; tv[3] = ta.w;
            tv[4] = tb.x; tv[5] = tb.y; tv[6] = tb.z; tv[7] = tb.w;
#pragma unroll
            for (int i = 0; i < 8; i++)
#pragma unroll
                for (int j = 0; j < 8; j++) acc[i][j] = fmaf(xv[i], tv[j], acc[i][j]);
        }
    }

    const int n = n0 + g;
#pragma unroll
    for (int bi = 0; bi < 8; bi++) {
        const int b = bq * 8 + bi;
        float* op = out + (((size_t)b * T_ + t) * N_ + n) * CO_ + oq * 8;
        float4 r0, r1;
        r0.x = fmaxf(acc[bi][0] + bias_s[g * 64 + oq * 8 + 0], 0.f);
        r0.y = fmaxf(acc[bi][1] + bias_s[g * 64 + oq * 8 + 1], 0.f);
        r0.z = fmaxf(acc[bi][2] + bias_s[g * 64 + oq * 8 + 2], 0.f);
        r0.w = fmaxf(acc[bi][3] + bias_s[g * 64 + oq * 8 + 3], 0.f);
        r1.x = fmaxf(acc[bi][4] + bias_s[g * 64 + oq * 8 + 4], 0.f);
        r1.y = fmaxf(acc[bi][5] + bias_s[g * 64 + oq * 8 + 5], 0.f);
        r1.z = fmaxf(acc[bi][6] + bias_s[g * 64 + oq * 8 + 6], 0.f);
        r1.w = fmaxf(acc[bi][7] + bias_s[g * 64 + oq * 8 + 7], 0.f);
        *(float4*)op       = r0;
        *(float4*)(op + 4) = r1;
    }
}

extern "C" void kernel_launch(void* const* d_in, const int* in_sizes, int n_in,
                              void* d_out, int out_size) {
    const float* x   = (const float*)d_in[0];  // [B,T,N,Ci]
    const float* emb = (const float*)d_in[1];  // [T,N,E]
    const float* W   = (const float*)d_in[2];  // [T,E,K,Ci,Co]
    const float* bp  = (const float*)d_in[3];  // [T,E,Co]
    float* out = (float*)d_out;                // [B,T,N,Co]

    cudaFuncSetAttribute(k_out, cudaFuncAttributeMaxDynamicSharedMemorySize,
                         SMEM_FLOATS * (int)sizeof(float));

    k_adj<<<dim3(N_ / 8, T_), 256>>>(emb);
    k_split<<<(B_ * T_ * N_ * CI_) / (256 * 4), 256>>>(x);
    k_spmm<<<dim3(N_ / 128, B_ * T_), 256>>>();
    k_out<<<dim3(N_ / 8, T_), 256, SMEM_FLOATS * sizeof(float)>>>(x, emb, W, bp, out);
}

// round 12
// speedup vs baseline: 1.7118x; 1.1647x over previous
#include <cuda_runtime.h>
#include <cuda_bf16.h>
#include <cstdint>

#define B_  32
#define T_  12
#define N_  512
#define E_  10
#define K_  3
#define CI_ 64
#define CO_ 64

// Scratch (static device globals -- allocation-free per harness rules)
__device__ float         g_diag2[T_ * N_];                    // 2 * diag(A), fp32
__device__ __nv_bfloat16 g_Ah[(size_t)T_ * N_ * N_];          // A hi (bf16)
__device__ __nv_bfloat16 g_Al[(size_t)T_ * N_ * N_];          // A lo (bf16)
__device__ __nv_bfloat16 g_xh[(size_t)B_ * T_ * N_ * CI_];    // x hi
__device__ __nv_bfloat16 g_xl[(size_t)B_ * T_ * N_ * CI_];    // x lo
__device__ float         g_xg1[(size_t)B_ * T_ * N_ * CI_];   // A@x propagated (fp32)

// ---------------------------------------------------------------------------
// Kernel 1: adjacency. Warp-per-row; block = 8 rows, emb[t] loaded once.
// ---------------------------------------------------------------------------
__global__ void __launch_bounds__(256) k_adj(const float* __restrict__ emb) {
    const int t    = blockIdx.y;
    const int wid  = threadIdx.x >> 5;
    const int lane = threadIdx.x & 31;
    const int n    = blockIdx.x * 8 + wid;

    __shared__ float se[N_ * E_];
    const float* et = emb + (size_t)t * N_ * E_;
    for (int i = threadIdx.x; i < N_ * E_; i += 256) se[i] = et[i];
    __syncthreads();

    float en[E_];
#pragma unroll
    for (int e = 0; e < E_; e++) en[e] = se[n * E_ + e];

    float v[16];
#pragma unroll
    for (int q = 0; q < 16; q++) {
        const int m = lane + 32 * q;
        float s = 0.f;
#pragma unroll
        for (int e = 0; e < E_; e++) s = fmaf(en[e], se[m * E_ + e], s);
        v[q] = fmaxf(s, 0.f);
    }

    float mx = v[0];
#pragma unroll
    for (int q = 1; q < 16; q++) mx = fmaxf(mx, v[q]);
#pragma unroll
    for (int o = 16; o > 0; o >>= 1) mx = fmaxf(mx, __shfl_xor_sync(0xffffffffu, mx, o));

    float sum = 0.f;
#pragma unroll
    for (int q = 0; q < 16; q++) {
        v[q] = expf(v[q] - mx);
        sum += v[q];
    }
#pragma unroll
    for (int o = 16; o > 0; o >>= 1) sum += __shfl_xor_sync(0xffffffffu, sum, o);
    const float inv = 1.0f / sum;

    const size_t base = ((size_t)t * N_ + n) * N_;
#pragma unroll
    for (int q = 0; q < 16; q++) {
        const float p = v[q] * inv;
        const __nv_bfloat16 h = __float2bfloat16(p);
        const __nv_bfloat16 l = __float2bfloat16(p - __bfloat162float(h));
        g_Ah[base + lane + 32 * q] = h;
        g_Al[base + lane + 32 * q] = l;
        if (q == (n >> 5) && lane == (n & 31))
            g_diag2[t * N_ + n] = 2.0f * p;
    }
}

// ---------------------------------------------------------------------------
// Kernel 1b: split x into bf16 hi/lo. 4 elems/thread, exact-size grid.
// ---------------------------------------------------------------------------
__global__ void __launch_bounds__(256) k_split(const float* __restrict__ x) {
    const size_t i = ((size_t)blockIdx.x * 256 + threadIdx.x) * 4;
    const float4 vv = *(const float4*)(x + i);
    float f[4];
    f[0] = vv.x; f[1] = vv.y; f[2] = vv.z; f[3] = vv.w;
    __nv_bfloat16 h[4], l[4];
#pragma unroll
    for (int j = 0; j < 4; j++) {
        h[j] = __float2bfloat16(f[j]);
        l[j] = __float2bfloat16(f[j] - __bfloat162float(h[j]));
    }
    *((__nv_bfloat162*)(g_xh + i))     = __halves2bfloat162(h[0], h[1]);
    *((__nv_bfloat162*)(g_xh + i + 2)) = __halves2bfloat162(h[2], h[3]);
    *((__nv_bfloat162*)(g_xl + i))     = __halves2bfloat162(l[0], l[1]);
    *((__nv_bfloat162*)(g_xl + i + 2)) = __halves2bfloat162(l[2], l[3]);
}

// ---------------------------------------------------------------------------
// mma helpers (shared by k_spmm and k_out)
// ---------------------------------------------------------------------------
__device__ __forceinline__ unsigned sptr(const void* p) {
    return (unsigned)__cvta_generic_to_shared(p);
}
__device__ __forceinline__ void ldsm4(unsigned* r, unsigned a) {
    asm volatile("ldmatrix.sync.aligned.m8n8.x4.shared.b16 {%0,%1,%2,%3}, [%4];"
                 : "=r"(r[0]), "=r"(r[1]), "=r"(r[2]), "=r"(r[3]) : "r"(a));
}
__device__ __forceinline__ void ldsm4t(unsigned* r, unsigned a) {
    asm volatile("ldmatrix.sync.aligned.m8n8.x4.trans.shared.b16 {%0,%1,%2,%3}, [%4];"
                 : "=r"(r[0]), "=r"(r[1]), "=r"(r[2]), "=r"(r[3]) : "r"(a));
}
__device__ __forceinline__ void mma16816(float* c, const unsigned* a, const unsigned* b) {
    asm volatile(
        "mma.sync.aligned.m16n8k16.row.col.f32.bf16.bf16.f32 "
        "{%0,%1,%2,%3}, {%4,%5,%6,%7}, {%8,%9}, {%0,%1,%2,%3};"
        : "+f"(c[0]), "+f"(c[1]), "+f"(c[2]), "+f"(c[3])
        : "r"(a[0]), "r"(a[1]), "r"(a[2]), "r"(a[3]), "r"(b[0]), "r"(b[1]));
}

// ---------------------------------------------------------------------------
// Kernel 2: xg1 = A @ x via mma.sync m16n8k16 bf16, 3-product split.
// ---------------------------------------------------------------------------
#define SA 40   // Ah_s row stride (bf16)
#define SX 72   // Xs row stride (bf16)

__global__ void __launch_bounds__(256) k_spmm() {
    const int bt = blockIdx.y;             // b*T + t
    const int t  = bt % T_;
    const int n0 = blockIdx.x * 128;

    __shared__ __align__(16) __nv_bfloat16 Ah_s[128 * SA];
    __shared__ __align__(16) __nv_bfloat16 Al_s[128 * SA];
    __shared__ __align__(16) __nv_bfloat16 Xh_s[32 * SX];
    __shared__ __align__(16) __nv_bfloat16 Xl_s[32 * SX];

    const int tid  = threadIdx.x;
    const int lane = tid & 31;
    const int warp = tid >> 5;
    const int wm   = (warp & 3) * 32;
    const int wn   = (warp >> 2) * 32;

    const int rA = tid >> 1;
    const int qA = (tid & 1) * 16;
    const int mX = tid >> 3;
    const int cX = (tid & 7) * 8;

    const __nv_bfloat16* gAh = g_Ah + ((size_t)t * N_ + n0 + rA) * N_;
    const __nv_bfloat16* gAl = g_Al + ((size_t)t * N_ + n0 + rA) * N_;
    const __nv_bfloat16* gXh = g_xh + ((size_t)bt * N_ + mX) * CI_ + cX;
    const __nv_bfloat16* gXl = g_xl + ((size_t)bt * N_ + mX) * CI_ + cX;

    float acc[2][4][4];
#pragma unroll
    for (int i = 0; i < 2; i++)
#pragma unroll
        for (int j = 0; j < 4; j++)
#pragma unroll
            for (int r = 0; r < 4; r++) acc[i][j][r] = 0.f;

    const int sub = lane >> 3;
    const int rl  = lane & 7;
    const int rAdd = ((sub & 1) << 3) + rl;
    const int cAdd = (sub >> 1) << 3;
    const unsigned baseAh = sptr(Ah_s);
    const unsigned baseAl = sptr(Al_s);
    const unsigned baseXh = sptr(Xh_s);
    const unsigned baseXl = sptr(Xl_s);

    uint4 pAh0, pAh1, pAl0, pAl1, pXh, pXl;

    pAh0 = *(const uint4*)(gAh + qA);
    pAh1 = *(const uint4*)(gAh + qA + 8);
    pAl0 = *(const uint4*)(gAl + qA);
    pAl1 = *(const uint4*)(gAl + qA + 8);
    pXh  = *(const uint4*)(gXh);
    pXl  = *(const uint4*)(gXl);
    *(uint4*)&Ah_s[rA * SA + qA]     = pAh0;
    *(uint4*)&Ah_s[rA * SA + qA + 8] = pAh1;
    *(uint4*)&Al_s[rA * SA + qA]     = pAl0;
    *(uint4*)&Al_s[rA * SA + qA + 8] = pAl1;
    *(uint4*)&Xh_s[mX * SX + cX]     = pXh;
    *(uint4*)&Xl_s[mX * SX + cX]     = pXl;
    __syncthreads();

    for (int c = 0; c < 16; c++) {
        if (c < 15) {
            const int m0 = (c + 1) * 32;
            pAh0 = *(const uint4*)(gAh + m0 + qA);
            pAh1 = *(const uint4*)(gAh + m0 + qA + 8);
            pAl0 = *(const uint4*)(gAl + m0 + qA);
            pAl1 = *(const uint4*)(gAl + m0 + qA + 8);
            pXh  = *(const uint4*)(gXh + (size_t)m0 * CI_);
            pXl  = *(const uint4*)(gXl + (size_t)m0 * CI_);
        }

#pragma unroll
        for (int s = 0; s < 2; s++) {
            unsigned ah[2][4], al[2][4], bh[2][4], bl[2][4];
#pragma unroll
            for (int i = 0; i < 2; i++) {
                const unsigned off =
                    (unsigned)(((wm + i * 16 + rAdd) * SA + s * 16 + cAdd) * 2);
                ldsm4(ah[i], baseAh + off);
                ldsm4(al[i], baseAl + off);
            }
#pragma unroll
            for (int jp = 0; jp < 2; jp++) {
                const unsigned off =
                    (unsigned)(((s * 16 + rAdd) * SX + wn + jp * 16 + cAdd) * 2);
                ldsm4t(bh[jp], baseXh + off);
                ldsm4t(bl[jp], baseXl + off);
            }
#pragma unroll
            for (int i = 0; i < 2; i++)
#pragma unroll
                for (int j = 0; j < 4; j++) {
                    const unsigned* bH = &bh[j >> 1][(j & 1) * 2];
                    const unsigned* bL = &bl[j >> 1][(j & 1) * 2];
                    mma16816(acc[i][j], ah[i], bH);
                    mma16816(acc[i][j], al[i], bH);
                    mma16816(acc[i][j], ah[i], bL);
                }
        }

        __syncthreads();
        if (c < 15) {
            *(uint4*)&Ah_s[rA * SA + qA]     = pAh0;
            *(uint4*)&Ah_s[rA * SA + qA + 8] = pAh1;
            *(uint4*)&Al_s[rA * SA + qA]     = pAl0;
            *(uint4*)&Al_s[rA * SA + qA + 8] = pAl1;
            *(uint4*)&Xh_s[mX * SX + cX]     = pXh;
            *(uint4*)&Xl_s[mX * SX + cX]     = pXl;
        }
        __syncthreads();
    }

    float* obase = g_xg1 + (size_t)bt * N_ * CI_;
#pragma unroll
    for (int i = 0; i < 2; i++)
#pragma unroll
        for (int j = 0; j < 4; j++) {
            const int row = n0 + wm + i * 16 + (lane >> 2);
            const int col = wn + j * 8 + (lane & 3) * 2;
            float2 lo, hi;
            lo.x = acc[i][j][0]; lo.y = acc[i][j][1];
            hi.x = acc[i][j][2]; hi.y = acc[i][j][3];
            *(float2*)(obase + (size_t)row * CI_ + col)       = lo;
            *(float2*)(obase + (size_t)(row + 8) * CI_ + col) = hi;
        }
}

// ---------------------------------------------------------------------------
// Kernel 3: fused theta-gen + output contraction on TENSOR CORES.
// Per chunk: stage xg (32b x 16kic) and theta (16kic x 64o) per node as bf16
// hi/lo in SMEM; each warp (= node) runs a 32x64x16 GEMM step via
// mma.m16n8k16 with 3-product split.
// ---------------------------------------------------------------------------
#define STH 72   // theta row stride (bf16): 64 + 8
#define SXG 24   // xg row stride (bf16): 16 + 8
#define KOUT_BF16  (2 * 8 * 16 * STH + 2 * 8 * 32 * SXG)
#define KOUT_BYTES (KOUT_BF16 * 2 + (512 + 96 + 8) * 4)

__global__ void __launch_bounds__(256, 2) k_out(const float* __restrict__ x,
                                                const float* __restrict__ emb,
                                                const float* __restrict__ W,
                                                const float* __restrict__ bp,
                                                float* __restrict__ out) {
    extern __shared__ __align__(16) char smraw[];
    __nv_bfloat16* thh = (__nv_bfloat16*)smraw;        // 8*16*STH
    __nv_bfloat16* thl = thh + 8 * 16 * STH;
    __nv_bfloat16* xgh = thl + 8 * 16 * STH;           // 8*32*SXG
    __nv_bfloat16* xgl = xgh + 8 * 32 * SXG;
    float* bias_s = (float*)(xgl + 8 * 32 * SXG);      // 512
    float* emb_s  = bias_s + 512;                      // 80 (pad 96)
    float* d2_s   = emb_s + 96;                        // 8

    const int t  = blockIdx.y;
    const int n0 = blockIdx.x * 8;
    const int tid = threadIdx.x;

    if (tid < 8 * E_)
        emb_s[tid] = emb[((size_t)t * N_ + n0 + tid / E_) * E_ + (tid % E_)];
    if (tid < 8) d2_s[tid] = g_diag2[t * N_ + n0 + tid];
    __syncthreads();

    for (int ii = tid; ii < 8 * CO_; ii += 256) {
        const int nl = ii >> 6;
        const int o  = ii & 63;
        float v = 0.f;
#pragma unroll
        for (int d = 0; d < E_; d++)
            v = fmaf(emb_s[nl * E_ + d], bp[((size_t)t * E_ + d) * CO_ + o], v);
        bias_s[ii] = v;
    }

    const int lane = tid & 31;
    const int g    = tid >> 5;          // node within tile (= warp)

    const int lnl = tid >> 5;
    const int lb  = tid & 31;           // staging: thread = (node lnl, batch lb)
    const float* xrow  = x     + (((size_t)lb * T_ + t) * N_ + n0 + lnl) * CI_;
    const float* x1row = g_xg1 + (((size_t)lb * T_ + t) * N_ + n0 + lnl) * CI_;
    const float d2 = d2_s[lnl];

    // theta-gen slot: 4 slots of (kic, o), stride 256
    const int kic0 = tid >> 6;
    const int oo   = tid & 63;

    // ldmatrix per-lane sub-tile offsets (same mapping as k_spmm)
    const int sub = lane >> 3;
    const int rl  = lane & 7;
    const int rAdd = ((sub & 1) << 3) + rl;
    const int cAdd = (sub >> 1) << 3;
    const unsigned baseTh = sptr(thh);
    const unsigned baseTl = sptr(thl);
    const unsigned baseXh = sptr(xgh);
    const unsigned baseXl = sptr(xgl);

    float acc[2][8][4];
#pragma unroll
    for (int i = 0; i < 2; i++)
#pragma unroll
        for (int j = 0; j < 8; j++)
#pragma unroll
            for (int r = 0; r < 4; r++) acc[i][j][r] = 0.f;

    for (int c = 0; c < 12; c++) {
        const int k  = c >> 2;
        const int i0 = (c & 3) * 16;
        __syncthreads();

        // --- stage xg chunk as bf16 hi/lo: rows = b, cols = kic ---
        {
            float xv[16];
#pragma unroll
            for (int j4 = 0; j4 < 4; j4++) {
                float4 f;
                if (k == 0) {
                    f = *(const float4*)(xrow + i0 + j4 * 4);
                } else if (k == 1) {
                    f = *(const float4*)(x1row + i0 + j4 * 4);
                } else {
                    float4 a  = *(const float4*)(x1row + i0 + j4 * 4);
                    float4 bb = *(const float4*)(xrow + i0 + j4 * 4);
                    f.x = fmaf(d2, a.x, -bb.x);
                    f.y = fmaf(d2, a.y, -bb.y);
                    f.z = fmaf(d2, a.z, -bb.z);
                    f.w = fmaf(d2, a.w, -bb.w);
                }
                xv[j4 * 4 + 0] = f.x;
                xv[j4 * 4 + 1] = f.y;
                xv[j4 * 4 + 2] = f.z;
                xv[j4 * 4 + 3] = f.w;
            }
            __nv_bfloat16* xh_row = xgh + (lnl * 32 + lb) * SXG;
            __nv_bfloat16* xl_row = xgl + (lnl * 32 + lb) * SXG;
#pragma unroll
            for (int jj = 0; jj < 16; jj++) {
                const __nv_bfloat16 h = __float2bfloat16(xv[jj]);
                xh_row[jj] = h;
                xl_row[jj] = __float2bfloat16(xv[jj] - __bfloat162float(h));
            }
        }

        // --- theta-gen (register-blocked over nodes), store bf16 hi/lo ---
        const float* wbase = W + (((size_t)t * E_ * K_ + k) * CI_ + i0) * CO_;
#pragma unroll 1
        for (int r = 0; r < 4; r++) {
            const int kic = kic0 + r * 4;
            const float* wp = wbase + kic * CO_ + oo;
            float th[8];
#pragma unroll
            for (int nl = 0; nl < 8; nl++) th[nl] = 0.f;
#pragma unroll
            for (int d = 0; d < E_; d++) {
                const float wv = wp[(size_t)d * (K_ * CI_ * CO_)];
#pragma unroll
                for (int nl = 0; nl < 8; nl++)
                    th[nl] = fmaf(emb_s[nl * E_ + d], wv, th[nl]);
            }
#pragma unroll
            for (int nl = 0; nl < 8; nl++) {
                const __nv_bfloat16 h = __float2bfloat16(th[nl]);
                thh[(nl * 16 + kic) * STH + oo] = h;
                thl[(nl * 16 + kic) * STH + oo] =
                    __float2bfloat16(th[nl] - __bfloat162float(h));
            }
        }
        __syncthreads();

        // --- tensor-core contraction: per warp, 32x64x16 GEMM step ---
        {
            unsigned ah[2][4], al[2][4], bh[4][4], bl[4][4];
#pragma unroll
            for (int i = 0; i < 2; i++) {
                const unsigned off =
                    (unsigned)(((g * 32 + i * 16 + rAdd) * SXG + cAdd) * 2);
                ldsm4(ah[i], baseXh + off);
                ldsm4(al[i], baseXl + off);
            }
#pragma unroll
            for (int jp = 0; jp < 4; jp++) {
                const unsigned off =
                    (unsigned)(((g * 16 + rAdd) * STH + jp * 16 + cAdd) * 2);
                ldsm4t(bh[jp], baseTh + off);
                ldsm4t(bl[jp], baseTl + off);
            }
#pragma unroll
            for (int i = 0; i < 2; i++)
#pragma unroll
                for (int j = 0; j < 8; j++) {
                    const unsigned* bH = &bh[j >> 1][(j & 1) * 2];
                    const unsigned* bL = &bl[j >> 1][(j & 1) * 2];
                    mma16816(acc[i][j], ah[i], bH);   // xh*th
                    mma16816(acc[i][j], al[i], bH);   // xl*th
                    mma16816(acc[i][j], ah[i], bL);   // xh*tl
                }
        }
    }

    // --- epilogue: relu(acc + bias) -> out[b,t,n,o] from c-fragments ---
    const int n = n0 + g;
#pragma unroll
    for (int j = 0; j < 8; j++) {
        const int col = j * 8 + (lane & 3) * 2;
        const float b0 = bias_s[g * 64 + col];
        const float b1 = bias_s[g * 64 + col + 1];
#pragma unroll
        for (int i = 0; i < 2; i++) {
            const int row0 = i * 16 + (lane >> 2);
            const int row1 = row0 + 8;
            float2 lo, hi;
            lo.x = fmaxf(acc[i][j][0] + b0, 0.f);
            lo.y = fmaxf(acc[i][j][1] + b1, 0.f);
            hi.x = fmaxf(acc[i][j][2] + b0, 0.f);
            hi.y = fmaxf(acc[i][j][3] + b1, 0.f);
            *(float2*)(out + (((size_t)row0 * T_ + t) * N_ + n) * CO_ + col) = lo;
            *(float2*)(out + (((size_t)row1 * T_ + t) * N_ + n) * CO_ + col) = hi;
        }
    }
}

extern "C" void kernel_launch(void* const* d_in, const int* in_sizes, int n_in,
                              void* d_out, int out_size) {
    const float* x   = (const float*)d_in[0];  // [B,T,N,Ci]
    const float* emb = (const float*)d_in[1];  // [T,N,E]
    const float* W   = (const float*)d_in[2];  // [T,E,K,Ci,Co]
    const float* bp  = (const float*)d_in[3];  // [T,E,Co]
    float* out = (float*)d_out;                // [B,T,N,Co]

    cudaFuncSetAttribute(k_out, cudaFuncAttributeMaxDynamicSharedMemorySize,
                         KOUT_BYTES);

    k_adj<<<dim3(N_ / 8, T_), 256>>>(emb);
    k_split<<<(B_ * T_ * N_ * CI_) / (256 * 4), 256>>>(x);
    k_spmm<<<dim3(N_ / 128, B_ * T_), 256>>>();
    k_out<<<dim3(N_ / 8, T_), 256, KOUT_BYTES>>>(x, emb, W, bp, out);
}